// round 7
// baseline (speedup 1.0000x reference)
#include <cuda_runtime.h>
#include <cstdint>

#define NODES   64
#define NINPUT  16
#define NOUT    8
#define NEDGE   256
#define BATCH   8192
#define PASSES  64
#define G       16            // edge slots per chunk (lanes per column)
#define TB      128           // threads per block
#define CPB     8             // columns per block (2 cols per warp)
#define GRIDB   (BATCH / CPB) // 1024 blocks
#define STRIDE  65            // floats per column (64 nodes + scratch row 64)
#define MAXCH   257           // worst case chunks + wrap chunk

__device__ uint2 g_recs[MAXCH * G + G];
__device__ int   g_nchunks;

// ---------------------------------------------------------------------------
// Serial first-fit bank-aware scheduler (lane 0; O(E) with short fit scans).
// Dependence rules for the sum-accumulation graph (proven in R6):
//   RAW:  read of src strictly after last chunk writing src
//   WAR:  write of dst strictly after last chunk reading dst
//   WAW-in-chunk: two writes of the same dst never share a chunk
//   WAW across chunks: unordered (fp adds commute; reassociation only)
// Placement = first chunk >= cmin with space, preferring
//   (dst bank free AND src bank free) > (dst bank free) > (any space);
// a new chunk is opened only when every legal chunk is full, so fill is
// never worse than the chunk-at-a-time greedy. Distinct dst banks cap the
// dst-load and dst-store at 2 wavefronts (cross-half offset only).
// rec.x = (dst_byte_off << 16) | src_byte_off, rec.y = w * 2*log2(e).
// ---------------------------------------------------------------------------
__global__ void sched_kernel(const float* __restrict__ wght,
                             const int*   __restrict__ src,
                             const int*   __restrict__ dst) {
    __shared__ int      ss[NEDGE], sd[NEDGE];
    __shared__ float    sw[NEDGE];
    __shared__ int      cwp[NODES], crp[NODES];   // next legal chunk (stored +1)
    __shared__ int      fill[NEDGE];
    __shared__ unsigned bm[NEDGE], rm[NEDGE];     // per-chunk dst/src bank masks
    __shared__ int      s_nch;
    const int lane = threadIdx.x;
    const float K2 = 2.8853900817779268f;  // 2 * log2(e)

    for (int e = lane; e < NEDGE; e += 32) {
        ss[e] = src[e]; sd[e] = dst[e]; sw[e] = wght[e] * K2;
        fill[e] = 0; bm[e] = 0u; rm[e] = 0u;
    }
    for (int n = lane; n < NODES; n += 32) { cwp[n] = 0; crp[n] = 0; }
    __syncwarp();

    if (lane == 0) {
        int nch = 0;
        for (int e = 0; e < NEDGE; e++) {
            const int s = ss[e], d = sd[e];
            int cmin = cwp[s];                       // RAW
            const int a = crp[d]; if (a > cmin) cmin = a;   // WAR
            const int b = cwp[d]; if (b > cmin) cmin = b;   // dst-write order
            const unsigned db = 1u << (d & 31);
            const unsigned sb = 1u << (s & 31);
            int pAny = -1, pBank = -1, pBoth = -1;
            for (int c = cmin; c < nch; c++) {
                if (fill[c] >= G) continue;
                if (pAny < 0) pAny = c;
                if (!(bm[c] & db)) {
                    if (pBank < 0) pBank = c;
                    if (!(rm[c] & sb)) { pBoth = c; break; }
                }
            }
            int place = (pBoth >= 0) ? pBoth : ((pBank >= 0) ? pBank : pAny);
            if (place < 0) place = nch++;
            const int slot = fill[place]++;
            bm[place] |= db; rm[place] |= sb;
            uint2 rec;
            rec.x = ((unsigned)(d * 4) << 16) | (unsigned)(s * 4);
            rec.y = __float_as_uint(sw[e]);
            g_recs[place * G + slot] = rec;
            if (place + 1 > cwp[d]) cwp[d] = place + 1;
            if (place + 1 > crp[s]) crp[s] = place + 1;
        }
        s_nch = nch;
        g_nchunks = nch;
    }
    __syncwarp();

    const int nch = s_nch;
    uint2 dummy; dummy.x = (256u << 16) | 256u;   // scratch row 64
    dummy.y = __float_as_uint(0.0f);              // tanh(0)=0 -> no-op
    for (int idx = lane; idx < nch * G; idx += 32) {
        const int c = idx >> 4, sl = idx & 15;
        if (sl >= fill[c]) g_recs[idx] = dummy;
    }
    __syncwarp();  // fence: all pad/lane-0 STGs visible before wrap copy
    for (int sl = lane; sl < G; sl += 32) g_recs[nch * G + sl] = g_recs[sl];
}

// ---------------------------------------------------------------------------
// Main kernel (R6 layout): warp = 2 columns x 16 edge slots. Node state
// [col][row] in smem, stride 65 floats. __syncwarp() orders smem between
// chunks. tanh(x) = 1 - 2/(exp2(x*2log2e)+1) via MUFU ex2/rcp.
// ---------------------------------------------------------------------------
__global__ void __launch_bounds__(TB, 1)
net_kernel(const float* __restrict__ x, float* __restrict__ out) {
    __shared__ float vals[CPB * STRIDE];

    const int tid  = threadIdx.x;
    const int lane = tid & 31;
    const int wid  = tid >> 5;
    const int cl   = wid * 2 + (lane >> 4);  // local column 0..7
    const int slot = lane & 15;
    const int bc   = blockIdx.x * CPB;

    for (int i = tid; i < CPB * NINPUT; i += TB) {
        const int r = i >> 3, c = i & 7;
        vals[c * STRIDE + r] = x[r * BATCH + bc + c];
    }
    for (int i = tid; i < CPB * (STRIDE - NINPUT); i += TB) {
        const int r = NINPUT + (i >> 3), c = i & 7;
        vals[c * STRIDE + r] = 0.0f;
    }
    __syncthreads();

    const int nch = g_nchunks;
    char* base = (char*)(vals + cl * STRIDE);

    uint2 rec = __ldg(&g_recs[slot]);
    #pragma unroll 1
    for (int p = 0; p < PASSES; p++) {
        #pragma unroll 2
        for (int c = 0; c < nch; c++) {
            const uint2 nxt = __ldg(&g_recs[(c + 1) * G + slot]);  // wrap=chunk0
            const unsigned sb = rec.x & 0xffffu;
            const unsigned db = rec.x >> 16;
            const float wv = __uint_as_float(rec.y);
            const float v  = *(const float*)(base + sb);
            const float t1 = *(const float*)(base + db) + 1.0f;
            const float a = v * wv;
            float ev;  asm("ex2.approx.f32 %0, %1;" : "=f"(ev) : "f"(a));
            float r2;  asm("rcp.approx.f32 %0, %1;" : "=f"(r2) : "f"(ev + 1.0f));
            *(float*)(base + db) = fmaf(-2.0f, r2, t1);  // pv + 1 - 2/(ev+1)
            rec = nxt;
            __syncwarp();
        }
    }
    __syncthreads();

    for (int i = tid; i < CPB * NOUT; i += TB) {
        const int r = i >> 3, c = i & 7;
        out[r * BATCH + bc + c] = tanhf(vals[c * STRIDE + NINPUT + r]);
    }
}

extern "C" void kernel_launch(void* const* d_in, const int* in_sizes, int n_in,
                              void* d_out, int out_size) {
    const float* x   = (const float*)d_in[0];
    const float* w   = (const float*)d_in[1];
    const int*   src = (const int*)d_in[2];
    const int*   dst = (const int*)d_in[3];
    (void)in_sizes; (void)n_in; (void)out_size;

    sched_kernel<<<1, 32>>>(w, src, dst);
    net_kernel<<<GRIDB, TB>>>(x, (float*)d_out);
}

// round 9
// speedup vs baseline: 1.3332x; 1.3332x over previous
#include <cuda_runtime.h>
#include <cstdint>

#define NODES   64
#define NINPUT  16
#define NOUT    8
#define NEDGE   256
#define BATCH   8192
#define PASSES  64
#define G       16            // edge slots per chunk (lanes per column)
#define TB      128           // threads per block
#define CPB     8             // columns per block (2 cols per warp)
#define GRIDB   (BATCH / CPB) // 1024 blocks
#define STRIDE  65            // floats per column (64 nodes + scratch row 64)
#define MAXCH   257           // worst case chunks + wrap chunk

__device__ uint2 g_recs[MAXCH * G + G];
__device__ int   g_nchunks;

// 64-bit inclusive OR-scan across the warp
__device__ __forceinline__ unsigned long long orscan_incl(unsigned long long x,
                                                          int lane) {
    #pragma unroll
    for (int o = 1; o < 32; o <<= 1) {
        unsigned lo = __shfl_up_sync(0xffffffffu, (unsigned)x, o);
        unsigned hi = __shfl_up_sync(0xffffffffu, (unsigned)(x >> 32), o);
        unsigned long long y = ((unsigned long long)hi << 32) | lo;
        if (lane >= o) x |= y;
    }
    return x;
}

__device__ __forceinline__ unsigned long long bcast64(unsigned long long x,
                                                      int srclane) {
    unsigned lo = __shfl_sync(0xffffffffu, (unsigned)x, srclane);
    unsigned hi = __shfl_sync(0xffffffffu, (unsigned)(x >> 32), srclane);
    return ((unsigned long long)hi << 32) | lo;
}

// ---------------------------------------------------------------------------
// Warp-parallel greedy list scheduler (R6 base) + bank-priority ACCEPTANCE:
// chunks still pack earliest-first (depth preserved); within a batch, ok
// candidates whose dst bank (dst mod 32) is new to the chunk are accepted
// first, so dst-load/store wavefronts approach the 2-wf floor.
// Dependence rules (proven in R6): RAW via W-footprint on src, WAR via
// R-footprint on dst, in-chunk dst distinctness; WAW across chunks relaxed
// (fp adds commute; reassociation only).
// rec.x = (dst_byte_off << 16) | src_byte_off, rec.y = w * 2*log2(e).
// ---------------------------------------------------------------------------
__global__ void sched_kernel(const float* __restrict__ wght,
                             const int*   __restrict__ src,
                             const int*   __restrict__ dst) {
    __shared__ int   ss[NEDGE], sd[NEDGE];
    __shared__ float sw[NEDGE];
    __shared__ short rlist[NEDGE], tmpl[NEDGE];
    __shared__ unsigned char accf[NEDGE];
    const int lane = threadIdx.x;
    const float K2 = 2.8853900817779268f;  // 2 * log2(e)

    for (int e = lane; e < NEDGE; e += 32) {
        ss[e] = src[e]; sd[e] = dst[e]; sw[e] = wght[e] * K2;
        rlist[e] = (short)e;
    }
    __syncwarp();

    const unsigned ltmask = (1u << lane) - 1u;
    uint2 dummy; dummy.x = (256u << 16) | 256u;  // scratch row 64
    dummy.y = __float_as_uint(0.0f);             // tanh(0)=0 -> no-op

    int nrem = NEDGE, nch = 0;
    while (nrem > 0) {
        // clear accept flags for every remaining position (scan may early-exit)
        for (int i = lane; i < nrem; i += 32) accf[i] = 0;
        __syncwarp();

        unsigned long long Wall = 0ull, Rall = 0ull, Wmem = 0ull;
        unsigned Bm = 0u;          // dst banks already used by chunk members
        int members = 0;
        for (int base = 0; base < nrem && members < G; base += 32) {
            const int  idx   = base + lane;
            const bool valid = idx < nrem;
            const int  e = valid ? rlist[idx] : 0;
            const int  s = ss[e], d = sd[e];
            const unsigned long long myW = valid ? (1ull << d) : 0ull;
            const unsigned long long myR = valid ? (1ull << s) : 0ull;
            const unsigned long long iW = orscan_incl(myW, lane);
            const unsigned long long iR = orscan_incl(myR, lane);
            unsigned lo = __shfl_up_sync(0xffffffffu, (unsigned)iW, 1);
            unsigned hi = __shfl_up_sync(0xffffffffu, (unsigned)(iW >> 32), 1);
            const unsigned long long eW =
                (lane == 0) ? 0ull : (((unsigned long long)hi << 32) | lo);
            lo = __shfl_up_sync(0xffffffffu, (unsigned)iR, 1);
            hi = __shfl_up_sync(0xffffffffu, (unsigned)(iR >> 32), 1);
            const unsigned long long eR =
                (lane == 0) ? 0ull : (((unsigned long long)hi << 32) | lo);

            const unsigned long long tWall = Wall | eW;  // excl scan, all W
            const unsigned long long tRall = Rall | eR;  // excl scan, all R
            const bool ok0 = valid &&
                             !((tWall >> s) & 1ull) &&
                             !((tRall >> d) & 1ull) &&
                             !((Wmem  >> d) & 1ull);
            // intra-batch member-dst dedup (keep lowest ok0 lane per dst)
            const unsigned peers = __match_any_sync(0xffffffffu, d);
            const unsigned bal0  = __ballot_sync(0xffffffffu, ok0);
            const bool ok = ok0 && ((peers & bal0 & ltmask) == 0u);

            // --- bank-priority two-round acceptance ---
            const unsigned bankbit = 1u << (d & 31);
            const unsigned balok   = __ballot_sync(0xffffffffu, ok);
            const unsigned bpeers  = __match_any_sync(0xffffffffu, d & 31);
            const bool firstbank = ok && ((bpeers & balok & ltmask) == 0u);
            const bool pri  = firstbank && !(Bm & bankbit);
            const unsigned bal1 = __ballot_sync(0xffffffffu, pri);
            const int  rank1 = members + __popc(bal1 & ltmask);
            const bool acc1  = pri && (rank1 < G);
            const int  m1 = members + __popc(__ballot_sync(0xffffffffu, acc1));
            const bool rest = ok && !pri;
            const unsigned bal2 = __ballot_sync(0xffffffffu, rest);
            const int  rank2 = m1 + __popc(bal2 & ltmask);
            const bool acc2  = rest && (rank2 < G);
            const bool accept = acc1 || acc2;
            const int  rank   = acc1 ? rank1 : rank2;

            if (accept) {
                uint2 rec;
                rec.x = ((unsigned)(d * 4) << 16) | (unsigned)(s * 4);
                rec.y = __float_as_uint(sw[e]);
                g_recs[nch * G + rank] = rec;
                accf[idx] = 1;
            }
            members = m1 + __popc(__ballot_sync(0xffffffffu, acc2));
            // fold footprints of everything scanned (conservative) + member sets
            Wall |= bcast64(iW, 31);
            Rall |= bcast64(iR, 31);
            const unsigned accWlo = __reduce_or_sync(0xffffffffu,
                accept ? (unsigned)(1ull << d) : 0u);
            const unsigned accWhi = __reduce_or_sync(0xffffffffu,
                accept ? (unsigned)((1ull << d) >> 32) : 0u);
            Wmem |= ((unsigned long long)accWhi << 32) | accWlo;
            Bm   |= __reduce_or_sync(0xffffffffu, accept ? bankbit : 0u);
        }
        if (lane >= members && lane < G) g_recs[nch * G + lane] = dummy;
        // compact remaining list (program order preserved)
        int wrpos = 0;
        for (int base = 0; base < nrem; base += 32) {
            const int  idx   = base + lane;
            const bool valid = idx < nrem;
            const int  e     = valid ? rlist[idx] : 0;
            const bool keep  = valid && !accf[idx];
            const unsigned kb = __ballot_sync(0xffffffffu, keep);
            if (keep) tmpl[wrpos + __popc(kb & ltmask)] = (short)e;
            wrpos += __popc(kb);
        }
        __syncwarp();
        for (int i = lane; i < wrpos; i += 32) rlist[i] = tmpl[i];
        __syncwarp();
        nrem = wrpos;
        nch++;
    }
    // wrap chunk = copy of chunk 0 (prefetch wrap-around)
    if (lane < G) g_recs[nch * G + lane] = g_recs[lane];
    if (lane == 0) g_nchunks = nch;
}

// ---------------------------------------------------------------------------
// Main kernel (R6 layout, best measured): warp = 2 columns x 16 edge slots.
// Node state [col][row] in smem, stride 65 floats. __syncwarp() orders smem
// between chunks. tanh(x) = 1 - 2/(exp2(x*2log2e)+1) via MUFU ex2/rcp.
// ---------------------------------------------------------------------------
__global__ void __launch_bounds__(TB, 1)
net_kernel(const float* __restrict__ x, float* __restrict__ out) {
    __shared__ float vals[CPB * STRIDE];

    const int tid  = threadIdx.x;
    const int lane = tid & 31;
    const int wid  = tid >> 5;
    const int cl   = wid * 2 + (lane >> 4);  // local column 0..7
    const int slot = lane & 15;
    const int bc   = blockIdx.x * CPB;

    for (int i = tid; i < CPB * NINPUT; i += TB) {
        const int r = i >> 3, c = i & 7;
        vals[c * STRIDE + r] = x[r * BATCH + bc + c];
    }
    for (int i = tid; i < CPB * (STRIDE - NINPUT); i += TB) {
        const int r = NINPUT + (i >> 3), c = i & 7;
        vals[c * STRIDE + r] = 0.0f;
    }
    __syncthreads();

    const int nch = g_nchunks;
    char* base = (char*)(vals + cl * STRIDE);

    uint2 rec = __ldg(&g_recs[slot]);
    #pragma unroll 1
    for (int p = 0; p < PASSES; p++) {
        #pragma unroll 2
        for (int c = 0; c < nch; c++) {
            const uint2 nxt = __ldg(&g_recs[(c + 1) * G + slot]);  // wrap=chunk0
            const unsigned sb = rec.x & 0xffffu;
            const unsigned db = rec.x >> 16;
            const float wv = __uint_as_float(rec.y);
            const float v  = *(const float*)(base + sb);
            const float t1 = *(const float*)(base + db) + 1.0f;
            const float a = v * wv;
            float ev;  asm("ex2.approx.f32 %0, %1;" : "=f"(ev) : "f"(a));
            float r2;  asm("rcp.approx.f32 %0, %1;" : "=f"(r2) : "f"(ev + 1.0f));
            *(float*)(base + db) = fmaf(-2.0f, r2, t1);  // pv + 1 - 2/(ev+1)
            rec = nxt;
            __syncwarp();
        }
    }
    __syncthreads();

    for (int i = tid; i < CPB * NOUT; i += TB) {
        const int r = i >> 3, c = i & 7;
        out[r * BATCH + bc + c] = tanhf(vals[c * STRIDE + NINPUT + r]);
    }
}

extern "C" void kernel_launch(void* const* d_in, const int* in_sizes, int n_in,
                              void* d_out, int out_size) {
    const float* x   = (const float*)d_in[0];
    const float* w   = (const float*)d_in[1];
    const int*   src = (const int*)d_in[2];
    const int*   dst = (const int*)d_in[3];
    (void)in_sizes; (void)n_in; (void)out_size;

    sched_kernel<<<1, 32>>>(w, src, dst);
    net_kernel<<<GRIDB, TB>>>(x, (float*)d_out);
}